// round 16
// baseline (speedup 1.0000x reference)
#include <cuda_runtime.h>

// ---------------------------------------------------------------------------
// WeightedInverseDistance (N=8192, D=3). Probe R16 — canonical XLA story:
//   r_k  = rn(1 / ls_k)            (XLA divide->reciprocal-multiply rewrite)
//   a_k  = rn(x_k * r_k)
//   sq   = (t0 + t1) + t2,  t_k = rn(a_k*a_k)   (reduce, no fma contraction)
//   G    = fma(a2,b2, fma(a1,b1, rn(a0*b0)))    (cublas k-loop, acc from 0)
//   d2   = rn( rn(sq_i + sq_j) - 2*G );  d = sqrt_rn(max(d2,0))
//   covar= (d + 1e-6)^(-p)   [p==2 fast path: rcp.approx((d+eps)^2)]
//   y_int= (covar@y)/(covar@1)   fused split-K during the covar sweep
// Output layout: [y_int (8192) | covar (8192*8192)] fp32.
// ---------------------------------------------------------------------------

constexpr int   KN      = 8192;
constexpr float KEPS    = 1e-6f;
constexpr int   NSPLIT  = 128;           // i-dimension splits
constexpr int   IPB     = KN / NSPLIT;   // 64 rows per split
constexpr int   NJBLK   = 8;             // 8 blocks * 256 thr * 4 cols = 8192 cols

__device__ float4 g_pts[KN];             // (xs0, xs1, xs2, sq)
__device__ float  g_yv [KN];             // y
__device__ float  g_num[NSPLIT][KN];
__device__ float  g_den[NSPLIT][KN];

__device__ __forceinline__ float rcpa(float x){ float r; asm("rcp.approx.f32 %0, %1;" : "=f"(r) : "f"(x)); return r; }

__global__ void prep_kernel(const float* __restrict__ x,
                            const float* __restrict__ y,
                            const float* __restrict__ ls)
{
    int i = blockIdx.x * blockDim.x + threadIdx.x;
    if (i < KN) {
        // a = x * rn(1/ls)   (XLA reciprocal-multiply rewrite)
        float r0 = __fdiv_rn(1.0f, ls[0]);
        float r1 = __fdiv_rn(1.0f, ls[1]);
        float r2 = __fdiv_rn(1.0f, ls[2]);
        float a0 = __fmul_rn(x[i * 3 + 0], r0);
        float a1 = __fmul_rn(x[i * 3 + 1], r1);
        float a2 = __fmul_rn(x[i * 3 + 2], r2);
        // sq: plain ascending reduce (t0+t1)+t2, products pre-rounded
        float t0 = __fmul_rn(a0, a0);
        float t1 = __fmul_rn(a1, a1);
        float t2 = __fmul_rn(a2, a2);
        float s  = __fadd_rn(__fadd_rn(t0, t1), t2);
        float4 p; p.x = a0; p.y = a1; p.z = a2; p.w = s;
        g_pts[i] = p;
        g_yv[i]  = y[i];
    }
}

// cublas-style ascending fma chain from zero accumulator:
//   acc = rn(a0*b0); acc = fma(a1,b1,acc); acc = fma(a2,b2,acc)
__device__ __forceinline__ float dotfasc(float ax, float ay, float az,
                                         float bx, float by, float bz)
{
    return __fmaf_rn(az, bz, __fmaf_rn(ay, by, __fmul_rn(ax, bx)));
}

__global__ void __launch_bounds__(256)
covar_kernel(float* __restrict__ covar, const float* __restrict__ power)
{
    const int j  = blockIdx.x * 1024 + threadIdx.x * 4;   // first of 4 columns
    const int i0 = blockIdx.y * IPB;
    const float p = power[0];

    float bx[4], by[4], bz[4], bs[4];
#pragma unroll
    for (int k = 0; k < 4; ++k) {
        float4 q = g_pts[j + k];
        bx[k] = q.x; by[k] = q.y; bz[k] = q.z; bs[k] = q.w;
    }

    float num[4] = {0.f, 0.f, 0.f, 0.f};
    float den[4] = {0.f, 0.f, 0.f, 0.f};

    const bool fast = (p == 2.0f);

    if (fast) {
#pragma unroll 4
        for (int i = i0; i < i0 + IPB; ++i) {
            const float4 pt = g_pts[i];    // warp-uniform, L1-hot
            const float  yi = g_yv[i];
            float c[4];
#pragma unroll
            for (int k = 0; k < 4; ++k) {
                float g  = dotfasc(pt.x, pt.y, pt.z, bx[k], by[k], bz[k]);
                float d2 = __fsub_rn(__fadd_rn(pt.w, bs[k]), __fadd_rn(g, g));
                d2 = fmaxf(d2, 0.0f);
                float d  = __fsqrt_rn(d2);
                float t  = __fadd_rn(d, KEPS);
                c[k] = rcpa(__fmul_rn(t, t));             // (d+eps)^-2
                num[k] = fmaf(c[k], yi, num[k]);
                den[k] += c[k];
            }
            float4 cv; cv.x = c[0]; cv.y = c[1]; cv.z = c[2]; cv.w = c[3];
            *reinterpret_cast<float4*>(covar + (size_t)i * KN + j) = cv;
        }
    } else {
        const float negp = -p;
#pragma unroll 2
        for (int i = i0; i < i0 + IPB; ++i) {
            const float4 pt = g_pts[i];
            const float  yi = g_yv[i];
            float c[4];
#pragma unroll
            for (int k = 0; k < 4; ++k) {
                float g  = dotfasc(pt.x, pt.y, pt.z, bx[k], by[k], bz[k]);
                float d2 = __fsub_rn(__fadd_rn(pt.w, bs[k]), __fadd_rn(g, g));
                d2 = fmaxf(d2, 0.0f);
                float d  = __fsqrt_rn(d2);
                float t  = __fadd_rn(d, KEPS);
                c[k] = powf(t, negp);                     // accurate generic path
                num[k] = fmaf(c[k], yi, num[k]);
                den[k] += c[k];
            }
            float4 cv; cv.x = c[0]; cv.y = c[1]; cv.z = c[2]; cv.w = c[3];
            *reinterpret_cast<float4*>(covar + (size_t)i * KN + j) = cv;
        }
    }

#pragma unroll
    for (int k = 0; k < 4; ++k) {
        g_num[blockIdx.y][j + k] = num[k];
        g_den[blockIdx.y][j + k] = den[k];
    }
}

__global__ void finalize_kernel(float* __restrict__ y_int)
{
    int j = blockIdx.x * blockDim.x + threadIdx.x;
    if (j < KN) {
        float num = 0.f, den = 0.f;
#pragma unroll 8
        for (int s = 0; s < NSPLIT; ++s) {
            num += g_num[s][j];
            den += g_den[s][j];
        }
        y_int[j] = num / den;
    }
}

extern "C" void kernel_launch(void* const* d_in, const int* in_sizes, int n_in,
                              void* d_out, int out_size)
{
    const float* x     = (const float*)d_in[0];   // [8192, 3]
    const float* y     = (const float*)d_in[1];   // [8192, 1]
    const float* ls    = (const float*)d_in[2];   // [3]
    const float* power = (const float*)d_in[3];   // [1]

    float* out   = (float*)d_out;
    float* y_int = out;        // first 8192 elements
    float* covar = out + KN;   // 8192*8192 elements

    prep_kernel<<<KN / 256, 256>>>(x, y, ls);
    covar_kernel<<<dim3(NJBLK, NSPLIT), 256>>>(covar, power);
    finalize_kernel<<<KN / 256, 256>>>(y_int);
}

// round 17
// speedup vs baseline: 1.0933x; 1.0933x over previous
#include <cuda_runtime.h>

// ---------------------------------------------------------------------------
// WeightedInverseDistance (N=8192, D=3) — symmetric tiled version.
// Bit-exact recipe (verified R16):
//   r_k = rn(1/ls_k); a_k = rn(x_k*r_k)
//   sq  = (t0+t1)+t2, t_k = rn(a_k*a_k)
//   G   = fma(a2,b2, fma(a1,b1, rn(a0*b0)))
//   d2  = rn(rn(sq_i+sq_j) - (G+G)); d = sqrt_rn(max(d2,0))
//   c   = rcp.approx((d+eps)^2)  [p==2]  /  powf(d+eps, -p) otherwise
// c_ij is bitwise symmetric -> compute upper-triangle tiles only, mirror via
// smem transpose. Row+col sums fused (split-slot partials), finalize divides.
// Output: [y_int (8192) | covar (8192*8192)] fp32.
// ---------------------------------------------------------------------------

constexpr int   KN    = 8192;
constexpr float KEPS  = 1e-6f;
constexpr int   TILE  = 128;
constexpr int   NT    = KN / TILE;            // 64 tile-rows
constexpr int   NPAIR = NT * (NT + 1) / 2;    // 2080 tile pairs

__device__ float g_num[NT][KN];
__device__ float g_den[NT][KN];

__device__ __forceinline__ float rcpa(float v){ float r; asm("rcp.approx.f32 %0, %1;" : "=f"(r) : "f"(v)); return r; }

struct Smem {
    float4 sp_row[TILE];    // row points (a0,a1,a2,sq)
    float  sy_row[TILE];
    float4 sp_col[TILE];    // col points
    float  sy_col[TILE];
    float  csm[32][132];    // 32-row transpose chunk (16B-aligned rows)
    float  red_num[8][TILE];
    float  red_den[8][TILE];
};

template<bool FAST>
__device__ __forceinline__ void covar_body(
    Smem& sm,
    const float* __restrict__ x, const float* __restrict__ yv,
    const float* __restrict__ ls, float negp,
    float* __restrict__ covar, int bi, int bj)
{
    const int tid  = threadIdx.x;
    const int lane = tid & 31;
    const int w    = tid >> 5;
    const bool diag = (bi == bj);

    // ---- setup: compute scaled points for this tile pair (recip-mul form) ----
    {
        float r0 = __fdiv_rn(1.0f, ls[0]);
        float r1 = __fdiv_rn(1.0f, ls[1]);
        float r2 = __fdiv_rn(1.0f, ls[2]);
        if (tid < TILE) {
            int jg = bj * TILE + tid;
            float a0 = __fmul_rn(x[jg*3+0], r0);
            float a1 = __fmul_rn(x[jg*3+1], r1);
            float a2 = __fmul_rn(x[jg*3+2], r2);
            float s  = __fadd_rn(__fadd_rn(__fmul_rn(a0,a0), __fmul_rn(a1,a1)), __fmul_rn(a2,a2));
            sm.sp_col[tid] = make_float4(a0, a1, a2, s);
            sm.sy_col[tid] = yv[jg];
        } else {
            int il = tid - TILE;
            int ig = bi * TILE + il;
            float a0 = __fmul_rn(x[ig*3+0], r0);
            float a1 = __fmul_rn(x[ig*3+1], r1);
            float a2 = __fmul_rn(x[ig*3+2], r2);
            float s  = __fadd_rn(__fadd_rn(__fmul_rn(a0,a0), __fmul_rn(a1,a1)), __fmul_rn(a2,a2));
            sm.sp_row[il] = make_float4(a0, a1, a2, s);
            sm.sy_row[il] = yv[ig];
        }
    }
    __syncthreads();

    // 4 columns per lane (registers)
    float bx[4], byy[4], bz[4], bsq[4], byj[4];
#pragma unroll
    for (int k = 0; k < 4; ++k) {
        float4 q = sm.sp_col[lane*4 + k];
        bx[k] = q.x; byy[k] = q.y; bz[k] = q.z; bsq[k] = q.w;
        byj[k] = sm.sy_col[lane*4 + k];
    }
    float cnum[4] = {0.f,0.f,0.f,0.f};
    float cden[4] = {0.f,0.f,0.f,0.f};
    float rnum = 0.f, rden = 0.f;      // per-lane row accumulators (row kk == lane)

    // ---- main loop: 4 chunks of 32 rows; warp w does rows ch*32 + w + 8m ----
    for (int ch = 0; ch < 4; ++ch) {
#pragma unroll
        for (int m = 0; m < 4; ++m) {
            const int il = ch*32 + w + 8*m;          // local row in [ch*32, ch*32+32)
            const float4 pt = sm.sp_row[il];
            const float  yi = sm.sy_row[il];
            float cc[4];
#pragma unroll
            for (int k = 0; k < 4; ++k) {
                float g  = __fmaf_rn(pt.z, bz[k], __fmaf_rn(pt.y, byy[k], __fmul_rn(pt.x, bx[k])));
                float d2 = __fsub_rn(__fadd_rn(pt.w, bsq[k]), __fadd_rn(g, g));
                d2 = fmaxf(d2, 0.0f);
                float d  = __fsqrt_rn(d2);
                float t  = __fadd_rn(d, KEPS);
                float cv;
                if (FAST) cv = rcpa(__fmul_rn(t, t));
                else      cv = powf(t, negp);
                cc[k] = cv;
                cnum[k] = __fmaf_rn(cv, yi, cnum[k]);
                cden[k] += cv;
            }
            float4 v4 = make_float4(cc[0], cc[1], cc[2], cc[3]);
            // direct (upper) tile store — coalesced
            *reinterpret_cast<float4*>(covar + (size_t)(bi*TILE + il)*KN + bj*TILE + lane*4) = v4;
            // stage for transpose
            *reinterpret_cast<float4*>(&sm.csm[w + 8*m][lane*4]) = v4;

            if (!diag) {
                // row partial over this lane's 4 cols, then warp butterfly
                float rpn = __fmaf_rn(cc[3], byj[3], __fmaf_rn(cc[2], byj[2],
                            __fmaf_rn(cc[1], byj[1], __fmul_rn(cc[0], byj[0]))));
                float rpd = __fadd_rn(__fadd_rn(cc[0], cc[1]), __fadd_rn(cc[2], cc[3]));
#pragma unroll
                for (int off = 16; off; off >>= 1) {
                    rpn += __shfl_xor_sync(0xffffffffu, rpn, off);
                    rpd += __shfl_xor_sync(0xffffffffu, rpd, off);
                }
                const int kk = ch*4 + m;             // 0..15
                if (lane == kk) { rnum += rpn; rden += rpd; }
            }
        }
        __syncthreads();
        if (!diag) {
            // transposed store of the 32-row chunk: covar[jg][ig-range], coalesced
#pragma unroll
            for (int r = 0; r < 4; ++r) {
                int idx = tid + 256*r;               // 0..1023
                int jl  = idx >> 3;                  // 0..127
                int i4  = idx & 7;                   // 0..7
                float4 v;
                v.x = sm.csm[i4*4+0][jl];
                v.y = sm.csm[i4*4+1][jl];
                v.z = sm.csm[i4*4+2][jl];
                v.w = sm.csm[i4*4+3][jl];
                *reinterpret_cast<float4*>(covar + (size_t)(bj*TILE + jl)*KN
                                           + bi*TILE + ch*32 + i4*4) = v;
            }
        }
        __syncthreads();
    }

    // ---- column partials: reduce 8 warps, write slot bi ----
#pragma unroll
    for (int k = 0; k < 4; ++k) {
        sm.red_num[w][lane*4 + k] = cnum[k];
        sm.red_den[w][lane*4 + k] = cden[k];
    }
    __syncthreads();
    if (tid < TILE) {
        float n = 0.f, d = 0.f;
#pragma unroll
        for (int ww = 0; ww < 8; ++ww) { n += sm.red_num[ww][tid]; d += sm.red_den[ww][tid]; }
        g_num[bi][bj*TILE + tid] = n;
        g_den[bi][bj*TILE + tid] = d;
    }
    // ---- row partials: write slot bj (off-diagonal pairs only) ----
    if (!diag && lane < 16) {
        int il = (lane >> 2)*32 + w + 8*(lane & 3);  // inverse of kk mapping
        g_num[bj][bi*TILE + il] = rnum;
        g_den[bj][bi*TILE + il] = rden;
    }
}

__global__ void __launch_bounds__(256, 3)
covar_sym_kernel(const float* __restrict__ x, const float* __restrict__ yv,
                 const float* __restrict__ ls, const float* __restrict__ power,
                 float* __restrict__ covar)
{
    __shared__ Smem sm;
    // decode blockIdx.x -> (bi, bj), bi <= bj
    int t = blockIdx.x;
    float disc = (2.0f*NT + 1.0f)*(2.0f*NT + 1.0f) - 8.0f*(float)t;
    int bi = (int)(((2.0f*NT + 1.0f) - sqrtf(disc)) * 0.5f);
    if (bi < 0) bi = 0;
    if (bi > NT-1) bi = NT-1;
    while (bi*NT - (bi*(bi-1))/2 > t) --bi;
    while (bi*NT - (bi*(bi-1))/2 + (NT - bi) <= t) ++bi;
    int bj = bi + (t - (bi*NT - (bi*(bi-1))/2));

    float p = power[0];
    if (p == 2.0f) covar_body<true >(sm, x, yv, ls, -p, covar, bi, bj);
    else           covar_body<false>(sm, x, yv, ls, -p, covar, bi, bj);
}

__global__ void finalize_kernel(float* __restrict__ y_int)
{
    int j = blockIdx.x * blockDim.x + threadIdx.x;
    if (j < KN) {
        float num = 0.f, den = 0.f;
#pragma unroll 8
        for (int s = 0; s < NT; ++s) {
            num += g_num[s][j];
            den += g_den[s][j];
        }
        y_int[j] = num / den;
    }
}

extern "C" void kernel_launch(void* const* d_in, const int* in_sizes, int n_in,
                              void* d_out, int out_size)
{
    const float* x     = (const float*)d_in[0];   // [8192, 3]
    const float* y     = (const float*)d_in[1];   // [8192, 1]
    const float* ls    = (const float*)d_in[2];   // [3]
    const float* power = (const float*)d_in[3];   // [1]

    float* out   = (float*)d_out;
    float* y_int = out;        // first 8192 elements
    float* covar = out + KN;   // 8192*8192 elements

    covar_sym_kernel<<<NPAIR, 256>>>(x, y, ls, power, covar);
    finalize_kernel<<<KN / 256, 256>>>(y_int);
}